// round 14
// baseline (speedup 1.0000x reference)
#include <cuda_runtime.h>
#include <cuda_bf16.h>

// ---------------------------------------------------------------------------
// Sparse 3D CNN (submanifold conv + masked maxpool pyramid).
// 64^3 -> 1^3, channels 3 -> 256.
// conv1 (sparse 64->64) + conv2..conv5 (dense D=32/16) run on tensor cores
// via warp-level mma.sync bf16 hi/lo-split 3-MMA (Ah*Bh + Al*Bh + Ah*Bl).
// conv_s0 emits bf16 hi/lo directly. Tail (D<=8) stays scalar fp32.
// ---------------------------------------------------------------------------

#define VOL0 (64 * 64 * 64)
#define MAXE (64 * 64 * 64 * 64)
#define GUARD 256

__device__ float g_bufA[MAXE + GUARD];  // [0,GUARD) stays zero forever
__device__ float g_bufB[MAXE + GUARD];
__device__ float g_maskA[VOL0];
__device__ float g_maskB[VOL0];
__device__ int   g_owner[VOL0];
__device__ int   g_list[VOL0];
__device__ int   g_cnt;

// bf16 split buffers (zero prefix; sized for level-0 64ch volume)
__device__ __nv_bfloat16 g_hi[GUARD + VOL0 * 64 + 64];
__device__ __nv_bfloat16 g_lo[GUARD + VOL0 * 64 + 64];
// prepacked B fragments: [tap][chunk][ntile][lane] -> uint2 {k0k1, k8k9}
__device__ uint2 g_pbh1[27 * 4 * 8 * 32];
__device__ uint2 g_pbl1[27 * 4 * 8 * 32];
__device__ uint2 g_pbh2[27 * 4 * 12 * 32];
__device__ uint2 g_pbl2[27 * 4 * 12 * 32];
__device__ uint2 g_pbh3[27 * 6 * 12 * 32];
__device__ uint2 g_pbl3[27 * 6 * 12 * 32];
__device__ uint2 g_pbh4[27 * 6 * 16 * 32];
__device__ uint2 g_pbl4[27 * 6 * 16 * 32];
__device__ uint2 g_pbh5[27 * 8 * 16 * 32];
__device__ uint2 g_pbl5[27 * 8 * 16 * 32];

// ---------------------------------------------------------------------------
__device__ __forceinline__ void mma_bf16(float* c, const unsigned* a, uint2 b) {
    asm volatile(
        "mma.sync.aligned.m16n8k16.row.col.f32.bf16.bf16.f32 "
        "{%0,%1,%2,%3}, {%4,%5,%6,%7}, {%8,%9}, {%0,%1,%2,%3};"
        : "+f"(c[0]), "+f"(c[1]), "+f"(c[2]), "+f"(c[3])
        : "r"(a[0]), "r"(a[1]), "r"(a[2]), "r"(a[3]), "r"(b.x), "r"(b.y));
}

// ======================== prologue kernels ================================
__global__ void k_scatter(const int* __restrict__ coors, int n, int* __restrict__ owner) {
    int i = blockIdx.x * blockDim.x + threadIdx.x;
    if (i == 0) g_cnt = 0;
    if (i >= n) return;
    int z = coors[3 * i], y = coors[3 * i + 1], x = coors[3 * i + 2];
    atomicMax(&owner[(z * 64 + y) * 64 + x], i + 1);
}

__global__ void k_build(const int* __restrict__ owner, float* __restrict__ mask) {
    int v = blockIdx.x * blockDim.x + threadIdx.x;
    if (v >= VOL0) return;
    int o = owner[v];
    mask[v] = (o > 0) ? 1.0f : 0.0f;
    if (o > 0) {
        int p = atomicAdd(&g_cnt, 1);
        g_list[p] = v;
    }
}

// fp32 -> bf16 hi/lo split
__global__ void k_split(const float* __restrict__ in, __nv_bfloat16* __restrict__ hi,
                        __nv_bfloat16* __restrict__ lo, int n) {
    int i = blockIdx.x * blockDim.x + threadIdx.x;
    if (i >= n) return;
    float x = in[i];
    __nv_bfloat16 h = __float2bfloat16(x);
    hi[i] = h;
    lo[i] = __float2bfloat16(x - __bfloat162float(h));
}

// Prepack B fragments: per (tap,chunk,ntile,lane) uint2 {bf16x2(k0,k0+1),
// bf16x2(k0+8,k0+9)} at n = nt*8 + lane/4, k0 = chunk*16 + (lane%4)*2.
__global__ void k_pb(const float* __restrict__ W, uint2* __restrict__ bh,
                     uint2* __restrict__ bl, int cin, int chunks, int ntiles,
                     int cout) {
    int i = blockIdx.x * blockDim.x + threadIdx.x;
    int total = 27 * chunks * ntiles * 32;
    if (i >= total) return;
    int lane = i & 31;
    int nt = (i >> 5) % ntiles;
    int c = (i / (32 * ntiles)) % chunks;
    int tap = i / (32 * ntiles * chunks);
    int g = lane >> 2, t = lane & 3;
    int n = nt * 8 + g;
    int k0 = c * 16 + t * 2;

    float w[4];
    w[0] = W[(tap * cin + k0 + 0) * cout + n];
    w[1] = W[(tap * cin + k0 + 1) * cout + n];
    w[2] = W[(tap * cin + k0 + 8) * cout + n];
    w[3] = W[(tap * cin + k0 + 9) * cout + n];

    __nv_bfloat162 h01, h89, l01, l89;
    h01.x = __float2bfloat16(w[0]);
    h01.y = __float2bfloat16(w[1]);
    h89.x = __float2bfloat16(w[2]);
    h89.y = __float2bfloat16(w[3]);
    l01.x = __float2bfloat16(w[0] - __bfloat162float(h01.x));
    l01.y = __float2bfloat16(w[1] - __bfloat162float(h01.y));
    l89.x = __float2bfloat16(w[2] - __bfloat162float(h89.x));
    l89.y = __float2bfloat16(w[3] - __bfloat162float(h89.y));

    uint2 ph, pl;
    ph.x = *reinterpret_cast<unsigned*>(&h01);
    ph.y = *reinterpret_cast<unsigned*>(&h89);
    pl.x = *reinterpret_cast<unsigned*>(&l01);
    pl.y = *reinterpret_cast<unsigned*>(&l89);
    bh[i] = ph;
    bl[i] = pl;
}

// ======================== conv0: sparse 3 -> 64, bf16 hi/lo out ===========
__global__ void __launch_bounds__(128) k_conv_s0(
    const int* __restrict__ owner, const float* __restrict__ feat,
    __nv_bfloat16* __restrict__ outH, __nv_bfloat16* __restrict__ outL,
    const float* __restrict__ W, const float* __restrict__ zp) {
    constexpr int VT = 10;
    const int lane = threadIdx.x & 31;
    const int vg = threadIdx.x >> 5;
    const int cnt = g_cnt;
    const int base = blockIdx.x * (4 * VT) + vg * VT;
    if (blockIdx.x * (4 * VT) >= cnt) return;

    int vids[VT];
#pragma unroll
    for (int i = 0; i < VT; i++) {
        int p = base + i;
        vids[i] = (p < cnt) ? g_list[p] : -1;
    }

    float2 acc[VT];
#pragma unroll
    for (int i = 0; i < VT; i++) { acc[i].x = 0.f; acc[i].y = 0.f; }

#pragma unroll 1
    for (int tap = 0; tap < 27; ++tap) {
        const int dz = tap / 9 - 1;
        const int dy = (tap / 3) % 3 - 1;
        const int dx = tap % 3 - 1;
        const int delta = dz * 4096 + dy * 64 + dx;
        const float2* wp = reinterpret_cast<const float2*>(W + tap * 3 * 64) + lane;
        float2 w0 = wp[0], w1 = wp[32], w2 = wp[64];

#pragma unroll
        for (int i = 0; i < VT; i++) {
            int v = vids[i];
            int x = v & 63, y = (v >> 6) & 63, z = v >> 12;
            bool inb = (v >= 0) & ((unsigned)(x + dx) < 64u) &
                       ((unsigned)(y + dy) < 64u) & ((unsigned)(z + dz) < 64u);
            int nv = v + delta;
            int o = inb ? owner[nv] : 0;
            const float* pf = (o > 0) ? feat + (o - 1) * 3 : zp;
            float a0 = pf[0], a1 = pf[1], a2 = pf[2];
            acc[i].x = fmaf(a0, w0.x, acc[i].x);
            acc[i].y = fmaf(a0, w0.y, acc[i].y);
            acc[i].x = fmaf(a1, w1.x, acc[i].x);
            acc[i].y = fmaf(a1, w1.y, acc[i].y);
            acc[i].x = fmaf(a2, w2.x, acc[i].x);
            acc[i].y = fmaf(a2, w2.y, acc[i].y);
        }
    }

#pragma unroll
    for (int i = 0; i < VT; i++) {
        if (vids[i] < 0) continue;
        __nv_bfloat162 h, l;
        h.x = __float2bfloat16(acc[i].x);
        h.y = __float2bfloat16(acc[i].y);
        l.x = __float2bfloat16(acc[i].x - __bfloat162float(h.x));
        l.y = __float2bfloat16(acc[i].y - __bfloat162float(h.y));
        int o = vids[i] * 64 + 2 * lane;
        *reinterpret_cast<__nv_bfloat162*>(outH + o) = h;
        *reinterpret_cast<__nv_bfloat162*>(outL + o) = l;
    }
}

// ======================== conv1: sparse 64 -> 64 via mma.sync =============
// Block = 128 thr = 4 warps; warp = M=16 list voxels; N=64 = 8 n-tiles;
// K = 27 taps x 64. Per-tap offsets via owner; inactive -> -GUARD (zeros).
__global__ void __launch_bounds__(128) k_convS(
    const int* __restrict__ owner,
    const __nv_bfloat16* __restrict__ inH, const __nv_bfloat16* __restrict__ inL,
    float* __restrict__ out,
    const uint2* __restrict__ Bh, const uint2* __restrict__ Bl) {
    const int cnt = g_cnt;
    if (blockIdx.x * 64 >= cnt) return;

    __shared__ int s_vid[64];
    __shared__ int s_off[64];

    const int tid = threadIdx.x;
    const int wid = tid >> 5;
    const int lane = tid & 31;
    const int g = lane >> 2;
    const int t2 = (lane & 3) * 2;
    const int r0 = wid * 16 + g;
    const int r1 = r0 + 8;

    if (tid < 64) {
        int p = blockIdx.x * 64 + tid;
        s_vid[tid] = (p < cnt) ? g_list[p] : -1;
    }
    __syncthreads();

    float acc[8][4];
#pragma unroll
    for (int nt = 0; nt < 8; nt++)
#pragma unroll
        for (int q = 0; q < 4; q++) acc[nt][q] = 0.f;

#pragma unroll 1
    for (int tap = 0; tap < 27; ++tap) {
        const int dz = tap / 9 - 1;
        const int dy = (tap / 3) % 3 - 1;
        const int dxx = tap % 3 - 1;
        const int delta = dz * 4096 + dy * 64 + dxx;

        __syncthreads();
        if (tid < 64) {
            int v = s_vid[tid];
            int x = v & 63, y = (v >> 6) & 63, z = v >> 12;
            bool inb = (v >= 0) & ((unsigned)(x + dxx) < 64u) &
                       ((unsigned)(y + dy) < 64u) & ((unsigned)(z + dz) < 64u);
            int nv = v + delta;
            int o = inb ? owner[nv] : 0;
            s_off[tid] = (o > 0) ? nv * 64 : -GUARD;
        }
        __syncthreads();

        const int o0 = s_off[r0];
        const int o1 = s_off[r1];

#pragma unroll 1
        for (int c = 0; c < 4; c++) {
            const int kb = c * 16 + t2;
            unsigned ah[4], al[4];
            ah[0] = *reinterpret_cast<const unsigned*>(inH + o0 + kb);
            ah[1] = *reinterpret_cast<const unsigned*>(inH + o1 + kb);
            ah[2] = *reinterpret_cast<const unsigned*>(inH + o0 + kb + 8);
            ah[3] = *reinterpret_cast<const unsigned*>(inH + o1 + kb + 8);
            al[0] = *reinterpret_cast<const unsigned*>(inL + o0 + kb);
            al[1] = *reinterpret_cast<const unsigned*>(inL + o1 + kb);
            al[2] = *reinterpret_cast<const unsigned*>(inL + o0 + kb + 8);
            al[3] = *reinterpret_cast<const unsigned*>(inL + o1 + kb + 8);

            const uint2* bhp = Bh + ((size_t)(tap * 4 + c) * 8) * 32 + lane;
            const uint2* blp = Bl + ((size_t)(tap * 4 + c) * 8) * 32 + lane;
#pragma unroll
            for (int nt = 0; nt < 8; nt++) {
                uint2 bh = bhp[nt * 32];
                uint2 bl = blp[nt * 32];
                mma_bf16(acc[nt], ah, bh);
                mma_bf16(acc[nt], al, bh);
                mma_bf16(acc[nt], ah, bl);
            }
        }
    }

    const int v0 = s_vid[r0];
    const int v1 = s_vid[r1];
#pragma unroll
    for (int nt = 0; nt < 8; nt++) {
        if (v0 >= 0) {
            float2 st;
            st.x = acc[nt][0];
            st.y = acc[nt][1];
            *reinterpret_cast<float2*>(out + (size_t)v0 * 64 + nt * 8 + t2) = st;
        }
        if (v1 >= 0) {
            float2 st;
            st.x = acc[nt][2];
            st.y = acc[nt][3];
            *reinterpret_cast<float2*>(out + (size_t)v1 * 64 + nt * 8 + t2) = st;
        }
    }
}

// ======================== dense mma conv (D=2^LOGD, COUT=NT*8) ============
template <int CIN, int LOGD, int NT>
__global__ void __launch_bounds__(128) k_convM(
    const __nv_bfloat16* __restrict__ inH, const __nv_bfloat16* __restrict__ inL,
    float* __restrict__ out,
    const uint2* __restrict__ Bh, const uint2* __restrict__ Bl,
    const float* __restrict__ mask) {
    constexpr int CH = CIN / 16;
    constexpr int COUT = NT * 8;
    constexpr int DD = 1 << LOGD;
    __shared__ int s_off[64];

    const int tid = threadIdx.x;
    const int wid = tid >> 5;
    const int lane = tid & 31;
    const int g = lane >> 2;
    const int t2 = (lane & 3) * 2;
    const int vb = blockIdx.x * 64;
    const int r0 = wid * 16 + g;
    const int r1 = r0 + 8;

    float acc[NT][4];
#pragma unroll
    for (int nt = 0; nt < NT; nt++)
#pragma unroll
        for (int q = 0; q < 4; q++) acc[nt][q] = 0.f;

#pragma unroll 1
    for (int tap = 0; tap < 27; ++tap) {
        const int dz = tap / 9 - 1;
        const int dy = (tap / 3) % 3 - 1;
        const int dxx = tap % 3 - 1;

        __syncthreads();
        if (tid < 64) {
            int v = vb + tid;
            int vx = v & (DD - 1), vy = (v >> LOGD) & (DD - 1), vz = v >> (2 * LOGD);
            bool ok = ((unsigned)(vx + dxx) < (unsigned)DD) &
                      ((unsigned)(vy + dy) < (unsigned)DD) &
                      ((unsigned)(vz + dz) < (unsigned)DD);
            int nv = v + (dz * DD + dy) * DD + dxx;
            s_off[tid] = ok ? nv * CIN : -GUARD;
        }
        __syncthreads();

        const int o0 = s_off[r0];
        const int o1 = s_off[r1];

#pragma unroll 1
        for (int c = 0; c < CH; c++) {
            const int kb = c * 16 + t2;
            unsigned ah[4], al[4];
            ah[0] = *reinterpret_cast<const unsigned*>(inH + o0 + kb);
            ah[1] = *reinterpret_cast<const unsigned*>(inH + o1 + kb);
            ah[2] = *reinterpret_cast<const unsigned*>(inH + o0 + kb + 8);
            ah[3] = *reinterpret_cast<const unsigned*>(inH + o1 + kb + 8);
            al[0] = *reinterpret_cast<const unsigned*>(inL + o0 + kb);
            al[1] = *reinterpret_cast<const unsigned*>(inL + o1 + kb);
            al[2] = *reinterpret_cast<const unsigned*>(inL + o0 + kb + 8);
            al[3] = *reinterpret_cast<const unsigned*>(inL + o1 + kb + 8);

            const uint2* bhp = Bh + ((size_t)(tap * CH + c) * NT) * 32 + lane;
            const uint2* blp = Bl + ((size_t)(tap * CH + c) * NT) * 32 + lane;
#pragma unroll
            for (int nt = 0; nt < NT; nt++) {
                uint2 bh = bhp[nt * 32];
                uint2 bl = blp[nt * 32];
                mma_bf16(acc[nt], ah, bh);
                mma_bf16(acc[nt], al, bh);
                mma_bf16(acc[nt], ah, bl);
            }
        }
    }

    const int v0 = vb + r0;
    const int v1 = vb + r1;
    const float m0 = mask[v0];
    const float m1 = mask[v1];
#pragma unroll
    for (int nt = 0; nt < NT; nt++) {
        float2 lo_st, hi_st;
        lo_st.x = acc[nt][0] * m0;
        lo_st.y = acc[nt][1] * m0;
        hi_st.x = acc[nt][2] * m1;
        hi_st.y = acc[nt][3] * m1;
        *reinterpret_cast<float2*>(out + (size_t)v0 * COUT + nt * 8 + t2) = lo_st;
        *reinterpret_cast<float2*>(out + (size_t)v1 * COUT + nt * 8 + t2) = hi_st;
    }
}

// ======================== scalar dense conv (tail) ========================
template <int CIN, int COUT, int WX, int WC, int COT, int XTT, bool CONTIG>
__global__ void __launch_bounds__(32 * WX * WC) k_convd(
    const float* __restrict__ in, float* __restrict__ out,
    const float* __restrict__ W, const float* __restrict__ mask, int D) {
    const int lane = threadIdx.x & 31;
    const int wrp = threadIdx.x >> 5;
    const int wc = wrp % WC;
    const int wx = wrp / WC;
    const int z = blockIdx.z, y = blockIdx.y;
    const int x0 = blockIdx.x * (WX * XTT) + wx * XTT;
    const int co0 = CONTIG ? (lane + 32 * wc) * COT : (lane + 32 * wc);

    float acc[XTT][COT];
#pragma unroll
    for (int i = 0; i < XTT; i++)
#pragma unroll
        for (int j = 0; j < COT; j++) acc[i][j] = 0.f;

#pragma unroll 1
    for (int r = 0; r < 9; r++) {
        const int dz = r / 3 - 1, dy = r % 3 - 1;
        const int zz = z + dz, yy = y + dy;
        if ((unsigned)zz >= (unsigned)D || (unsigned)yy >= (unsigned)D) continue;
        const int rowbase = ((zz * D + yy) * D) * CIN;

        int ox[XTT + 2];
#pragma unroll
        for (int i = 0; i < XTT + 2; i++) {
            int gx = x0 - 1 + i;
            ox[i] = ((unsigned)gx < (unsigned)D) ? rowbase + gx * CIN : -GUARD;
        }

#pragma unroll 1
        for (int c = 0; c < CIN; c += 4) {
            float4 a[XTT + 2];
#pragma unroll
            for (int i = 0; i < XTT + 2; i++)
                a[i] = *reinterpret_cast<const float4*>(in + ox[i] + c);
#pragma unroll
            for (int dx = 0; dx < 3; dx++) {
                const float* wp = W + (size_t)((r * 3 + dx) * CIN) * COUT + co0;
                float wv[4][COT];
#pragma unroll
                for (int q = 0; q < 4; q++) {
                    if (CONTIG && COT == 2) {
                        float2 tt = *reinterpret_cast<const float2*>(wp + (c + q) * COUT);
                        wv[q][0] = tt.x;
                        wv[q][1] = tt.y;
                    } else {
#pragma unroll
                        for (int j = 0; j < COT; j++)
                            wv[q][j] = wp[(c + q) * COUT + j * 32 * WC];
                    }
                }
#pragma unroll
                for (int i = 0; i < XTT; i++) {
#pragma unroll
                    for (int j = 0; j < COT; j++) {
                        acc[i][j] = fmaf(a[i + dx].x, wv[0][j], acc[i][j]);
                        acc[i][j] = fmaf(a[i + dx].y, wv[1][j], acc[i][j]);
                        acc[i][j] = fmaf(a[i + dx].z, wv[2][j], acc[i][j]);
                        acc[i][j] = fmaf(a[i + dx].w, wv[3][j], acc[i][j]);
                    }
                }
            }
        }
    }

    const int vb = (z * D + y) * D;
#pragma unroll
    for (int i = 0; i < XTT; i++) {
        int gx = x0 + i;
        float m = mask[vb + gx];
        float* op = out + (size_t)(vb + gx) * COUT + co0;
        if (CONTIG && COT == 2) {
            float2 tt;
            tt.x = acc[i][0] * m;
            tt.y = acc[i][1] * m;
            *reinterpret_cast<float2*>(op) = tt;
        } else {
#pragma unroll
            for (int j = 0; j < COT; j++) op[j * 32 * WC] = acc[i][j] * m;
        }
    }
}

// ======================== masked 2x2x2 max pool ===========================
__global__ void k_pool(const float* __restrict__ in, const float* __restrict__ im,
                       float* __restrict__ out, float* __restrict__ om,
                       int Do, int C) {
    int idx = blockIdx.x * blockDim.x + threadIdx.x;
    int total = Do * Do * Do * C;
    if (idx >= total) return;
    int c = idx % C;
    int v = idx / C;
    int xo = v % Do;
    int yo = (v / Do) % Do;
    int zo = v / (Do * Do);
    int Di = Do * 2;
    float best = -3.4e38f;
    bool any = false;
#pragma unroll
    for (int a = 0; a < 2; a++)
#pragma unroll
        for (int b = 0; b < 2; b++)
#pragma unroll
            for (int d = 0; d < 2; d++) {
                int vi = ((2 * zo + a) * Di + (2 * yo + b)) * Di + (2 * xo + d);
                if (im[vi] > 0.f) {
                    any = true;
                    float t = in[vi * C + c];
                    best = t > best ? t : best;
                }
            }
    out[v * C + c] = any ? best : 0.f;
    if (c == 0) om[v] = any ? 1.f : 0.f;
}

// ---------------------------------------------------------------------------
extern "C" void kernel_launch(void* const* d_in, const int* in_sizes, int n_in,
                              void* d_out, int out_size) {
    const float* feat = (const float*)d_in[0];
    const int* coors = (const int*)d_in[1];
    const float* W[14];
    for (int i = 0; i < 14; i++) W[i] = (const float*)d_in[2 + i];

    float *A, *B, *MA, *MB, *ZP;
    int* OWN;
    __nv_bfloat16 *HI, *LO;
    uint2 *PBH1, *PBL1, *PBH2, *PBL2, *PBH3, *PBL3, *PBH4, *PBL4, *PBH5, *PBL5;
    cudaGetSymbolAddress((void**)&A, g_bufA);
    cudaGetSymbolAddress((void**)&B, g_bufB);
    cudaGetSymbolAddress((void**)&MA, g_maskA);
    cudaGetSymbolAddress((void**)&MB, g_maskB);
    cudaGetSymbolAddress((void**)&OWN, g_owner);
    cudaGetSymbolAddress((void**)&HI, g_hi);
    cudaGetSymbolAddress((void**)&LO, g_lo);
    cudaGetSymbolAddress((void**)&PBH1, g_pbh1);
    cudaGetSymbolAddress((void**)&PBL1, g_pbl1);
    cudaGetSymbolAddress((void**)&PBH2, g_pbh2);
    cudaGetSymbolAddress((void**)&PBL2, g_pbl2);
    cudaGetSymbolAddress((void**)&PBH3, g_pbh3);
    cudaGetSymbolAddress((void**)&PBL3, g_pbl3);
    cudaGetSymbolAddress((void**)&PBH4, g_pbh4);
    cudaGetSymbolAddress((void**)&PBL4, g_pbl4);
    cudaGetSymbolAddress((void**)&PBH5, g_pbh5);
    cudaGetSymbolAddress((void**)&PBL5, g_pbl5);
    ZP = A;      // zero prefix of g_bufA doubles as conv_s0's zero page
    A += GUARD;
    B += GUARD;

    const int N = in_sizes[0] / 3;
    const int sb = (N + 39) / 40;
    const int sbM = (N + 63) / 64;

    // Weight prepacks (depend only on W inputs)
    k_pb<<<(27 * 4 * 8 * 32 + 255) / 256, 256>>>(W[1], PBH1, PBL1, 64, 4, 8, 64);
    k_pb<<<(27 * 4 * 12 * 32 + 255) / 256, 256>>>(W[2], PBH2, PBL2, 64, 4, 12, 96);
    k_pb<<<(27 * 6 * 12 * 32 + 255) / 256, 256>>>(W[3], PBH3, PBL3, 96, 6, 12, 96);
    k_pb<<<(27 * 6 * 16 * 32 + 255) / 256, 256>>>(W[4], PBH4, PBL4, 96, 6, 16, 128);
    k_pb<<<(27 * 8 * 16 * 32 + 255) / 256, 256>>>(W[5], PBH5, PBL5, 128, 8, 16, 128);

    k_scatter<<<(N + 255) / 256, 256>>>(coors, N, OWN);
    k_build<<<(VOL0 + 255) / 256, 256>>>(OWN, MA);

    // Level 0: conv0 -> bf16 hi/lo, conv1 via sparse mma -> A (fp32)
    k_conv_s0<<<sb, 128>>>(OWN, feat, HI + GUARD, LO + GUARD, W[0], ZP);
    k_convS<<<sbM, 128>>>(OWN, HI + GUARD, LO + GUARD, A, PBH1, PBL1);
    k_pool<<<(32 * 32 * 32 * 64 + 255) / 256, 256>>>(A, MA, B, MB, 32, 64);

    // D=32: dense mma convs
    k_split<<<(32768 * 64 + 255) / 256, 256>>>(B, HI + GUARD, LO + GUARD, 32768 * 64);
    k_convM<64, 5, 12><<<512, 128>>>(HI + GUARD, LO + GUARD, A, PBH2, PBL2, MB);
    k_split<<<(32768 * 96 + 255) / 256, 256>>>(A, HI + GUARD, LO + GUARD, 32768 * 96);
    k_convM<96, 5, 12><<<512, 128>>>(HI + GUARD, LO + GUARD, B, PBH3, PBL3, MB);
    k_pool<<<(16 * 16 * 16 * 96 + 255) / 256, 256>>>(B, MB, A, MA, 16, 96);

    // D=16: dense mma convs
    k_split<<<(4096 * 96 + 255) / 256, 256>>>(A, HI + GUARD, LO + GUARD, 4096 * 96);
    k_convM<96, 4, 16><<<64, 128>>>(HI + GUARD, LO + GUARD, B, PBH4, PBL4, MA);
    k_split<<<(4096 * 128 + 255) / 256, 256>>>(B, HI + GUARD, LO + GUARD, 4096 * 128);
    k_convM<128, 4, 16><<<64, 128>>>(HI + GUARD, LO + GUARD, A, PBH5, PBL5, MA);
    k_pool<<<(8 * 8 * 8 * 128 + 255) / 256, 256>>>(A, MA, B, MB, 8, 128);

    // D=8 (scalar tail)
    k_convd<128, 160, 1, 5, 1, 1, false><<<dim3(8, 8, 8), 160>>>(B, A, W[6], MB, 8);
    k_convd<160, 160, 1, 5, 1, 1, false><<<dim3(8, 8, 8), 160>>>(A, B, W[7], MB, 8);
    k_pool<<<(4 * 4 * 4 * 160 + 255) / 256, 256>>>(B, MB, A, MA, 4, 160);

    // D=4
    k_convd<160, 192, 1, 3, 2, 1, true><<<dim3(4, 4, 4), 96>>>(A, B, W[8], MA, 4);
    k_convd<192, 192, 1, 3, 2, 1, true><<<dim3(4, 4, 4), 96>>>(B, A, W[9], MA, 4);
    k_pool<<<(2 * 2 * 2 * 192 + 255) / 256, 256>>>(A, MA, B, MB, 2, 192);

    // D=2
    k_convd<192, 224, 1, 7, 1, 1, false><<<dim3(2, 2, 2), 224>>>(B, A, W[10], MB, 2);
    k_convd<224, 224, 1, 7, 1, 1, false><<<dim3(2, 2, 2), 224>>>(A, B, W[11], MB, 2);
    k_pool<<<(1 * 224 + 255) / 256, 256>>>(B, MB, A, MA, 1, 224);

    // D=1 -> final output straight into d_out
    k_convd<224, 256, 1, 4, 2, 1, true><<<dim3(1, 1, 1), 128>>>(A, B, W[12], MA, 1);
    k_convd<256, 256, 1, 4, 2, 1, true><<<dim3(1, 1, 1), 128>>>(B, (float*)d_out, W[13], MA, 1);
}

// round 15
// speedup vs baseline: 1.0615x; 1.0615x over previous
#include <cuda_runtime.h>
#include <cuda_bf16.h>

// ---------------------------------------------------------------------------
// Sparse 3D CNN (submanifold conv + masked maxpool pyramid).
// 64^3 -> 1^3, channels 3 -> 256.
// conv2..conv5 (dense D=32/16) on tensor cores via mma.sync bf16 hi/lo-split
// 3-MMA. D=32 kernels use M=32/warp (B fragments reused across 6 MMAs).
// conv0/conv1 + tail (D<=8) stay scalar fp32 (proven fastest forms).
// ---------------------------------------------------------------------------

#define VOL0 (64 * 64 * 64)
#define MAXE (64 * 64 * 64 * 64)
#define GUARD 256

__device__ float g_bufA[MAXE + GUARD];  // [0,GUARD) stays zero forever
__device__ float g_bufB[MAXE + GUARD];
__device__ float g_maskA[VOL0];
__device__ float g_maskB[VOL0];
__device__ int   g_owner[VOL0];
__device__ int   g_list[VOL0];
__device__ int   g_cnt;

// bf16 split buffers (zero prefix + pad)
__device__ __nv_bfloat16 g_hi[GUARD + 32768 * 96 + 64];
__device__ __nv_bfloat16 g_lo[GUARD + 32768 * 96 + 64];
// prepacked B fragments: [tap][chunk][ntile][lane] -> uint2 {k0k1, k8k9}
__device__ uint2 g_pbh2[27 * 4 * 12 * 32];
__device__ uint2 g_pbl2[27 * 4 * 12 * 32];
__device__ uint2 g_pbh3[27 * 6 * 12 * 32];
__device__ uint2 g_pbl3[27 * 6 * 12 * 32];
__device__ uint2 g_pbh4[27 * 6 * 16 * 32];
__device__ uint2 g_pbl4[27 * 6 * 16 * 32];
__device__ uint2 g_pbh5[27 * 8 * 16 * 32];
__device__ uint2 g_pbl5[27 * 8 * 16 * 32];

// ---------------------------------------------------------------------------
__device__ __forceinline__ void mma_bf16(float* c, const unsigned* a, uint2 b) {
    asm volatile(
        "mma.sync.aligned.m16n8k16.row.col.f32.bf16.bf16.f32 "
        "{%0,%1,%2,%3}, {%4,%5,%6,%7}, {%8,%9}, {%0,%1,%2,%3};"
        : "+f"(c[0]), "+f"(c[1]), "+f"(c[2]), "+f"(c[3])
        : "r"(a[0]), "r"(a[1]), "r"(a[2]), "r"(a[3]), "r"(b.x), "r"(b.y));
}

// ======================== prologue kernels ================================
__global__ void k_scatter(const int* __restrict__ coors, int n, int* __restrict__ owner) {
    int i = blockIdx.x * blockDim.x + threadIdx.x;
    if (i == 0) g_cnt = 0;
    if (i >= n) return;
    int z = coors[3 * i], y = coors[3 * i + 1], x = coors[3 * i + 2];
    atomicMax(&owner[(z * 64 + y) * 64 + x], i + 1);
}

__global__ void k_build(const int* __restrict__ owner, float* __restrict__ mask) {
    int v = blockIdx.x * blockDim.x + threadIdx.x;
    if (v >= VOL0) return;
    int o = owner[v];
    mask[v] = (o > 0) ? 1.0f : 0.0f;
    if (o > 0) {
        int p = atomicAdd(&g_cnt, 1);
        g_list[p] = v;
    }
}

// fp32 -> bf16 hi/lo split
__global__ void k_split(const float* __restrict__ in, __nv_bfloat16* __restrict__ hi,
                        __nv_bfloat16* __restrict__ lo, int n) {
    int i = blockIdx.x * blockDim.x + threadIdx.x;
    if (i >= n) return;
    float x = in[i];
    __nv_bfloat16 h = __float2bfloat16(x);
    hi[i] = h;
    lo[i] = __float2bfloat16(x - __bfloat162float(h));
}

// Prepack B fragments: per (tap,chunk,ntile,lane) uint2 {bf16x2(k0,k0+1),
// bf16x2(k0+8,k0+9)} at n = nt*8 + lane/4, k0 = chunk*16 + (lane%4)*2.
__global__ void k_pb(const float* __restrict__ W, uint2* __restrict__ bh,
                     uint2* __restrict__ bl, int cin, int chunks, int ntiles,
                     int cout) {
    int i = blockIdx.x * blockDim.x + threadIdx.x;
    int total = 27 * chunks * ntiles * 32;
    if (i >= total) return;
    int lane = i & 31;
    int nt = (i >> 5) % ntiles;
    int c = (i / (32 * ntiles)) % chunks;
    int tap = i / (32 * ntiles * chunks);
    int g = lane >> 2, t = lane & 3;
    int n = nt * 8 + g;
    int k0 = c * 16 + t * 2;

    float w[4];
    w[0] = W[(tap * cin + k0 + 0) * cout + n];
    w[1] = W[(tap * cin + k0 + 1) * cout + n];
    w[2] = W[(tap * cin + k0 + 8) * cout + n];
    w[3] = W[(tap * cin + k0 + 9) * cout + n];

    __nv_bfloat162 h01, h89, l01, l89;
    h01.x = __float2bfloat16(w[0]);
    h01.y = __float2bfloat16(w[1]);
    h89.x = __float2bfloat16(w[2]);
    h89.y = __float2bfloat16(w[3]);
    l01.x = __float2bfloat16(w[0] - __bfloat162float(h01.x));
    l01.y = __float2bfloat16(w[1] - __bfloat162float(h01.y));
    l89.x = __float2bfloat16(w[2] - __bfloat162float(h89.x));
    l89.y = __float2bfloat16(w[3] - __bfloat162float(h89.y));

    uint2 ph, pl;
    ph.x = *reinterpret_cast<unsigned*>(&h01);
    ph.y = *reinterpret_cast<unsigned*>(&h89);
    pl.x = *reinterpret_cast<unsigned*>(&l01);
    pl.y = *reinterpret_cast<unsigned*>(&l89);
    bh[i] = ph;
    bl[i] = pl;
}

// ======================== scalar sparse convs (level 0) ===================
__global__ void __launch_bounds__(128) k_conv_s0(
    const int* __restrict__ owner, const float* __restrict__ feat,
    float* __restrict__ out, const float* __restrict__ W,
    const float* __restrict__ zp) {
    constexpr int VT = 10;
    const int lane = threadIdx.x & 31;
    const int vg = threadIdx.x >> 5;
    const int cnt = g_cnt;
    const int base = blockIdx.x * (4 * VT) + vg * VT;
    if (blockIdx.x * (4 * VT) >= cnt) return;

    int vids[VT];
#pragma unroll
    for (int i = 0; i < VT; i++) {
        int p = base + i;
        vids[i] = (p < cnt) ? g_list[p] : -1;
    }

    float2 acc[VT];
#pragma unroll
    for (int i = 0; i < VT; i++) { acc[i].x = 0.f; acc[i].y = 0.f; }

#pragma unroll 1
    for (int tap = 0; tap < 27; ++tap) {
        const int dz = tap / 9 - 1;
        const int dy = (tap / 3) % 3 - 1;
        const int dx = tap % 3 - 1;
        const int delta = dz * 4096 + dy * 64 + dx;
        const float2* wp = reinterpret_cast<const float2*>(W + tap * 3 * 64) + lane;
        float2 w0 = wp[0], w1 = wp[32], w2 = wp[64];

#pragma unroll
        for (int i = 0; i < VT; i++) {
            int v = vids[i];
            int x = v & 63, y = (v >> 6) & 63, z = v >> 12;
            bool inb = (v >= 0) & ((unsigned)(x + dx) < 64u) &
                       ((unsigned)(y + dy) < 64u) & ((unsigned)(z + dz) < 64u);
            int nv = v + delta;
            int o = inb ? owner[nv] : 0;
            const float* pf = (o > 0) ? feat + (o - 1) * 3 : zp;
            float a0 = pf[0], a1 = pf[1], a2 = pf[2];
            acc[i].x = fmaf(a0, w0.x, acc[i].x);
            acc[i].y = fmaf(a0, w0.y, acc[i].y);
            acc[i].x = fmaf(a1, w1.x, acc[i].x);
            acc[i].y = fmaf(a1, w1.y, acc[i].y);
            acc[i].x = fmaf(a2, w2.x, acc[i].x);
            acc[i].y = fmaf(a2, w2.y, acc[i].y);
        }
    }

#pragma unroll
    for (int i = 0; i < VT; i++)
        if (vids[i] >= 0)
            *reinterpret_cast<float2*>(out + vids[i] * 64 + 2 * lane) = acc[i];
}

__global__ void __launch_bounds__(128) k_conv_s64(
    const int* __restrict__ owner, const float* __restrict__ in,
    float* __restrict__ out, const float* __restrict__ W) {
    constexpr int VT = 10;
    const int lane = threadIdx.x & 31;
    const int vg = threadIdx.x >> 5;
    const int cnt = g_cnt;
    const int base = blockIdx.x * (4 * VT) + vg * VT;
    if (blockIdx.x * (4 * VT) >= cnt) return;

    int vids[VT];
#pragma unroll
    for (int i = 0; i < VT; i++) {
        int p = base + i;
        vids[i] = (p < cnt) ? g_list[p] : -1;
    }

    float2 acc[VT];
#pragma unroll
    for (int i = 0; i < VT; i++) { acc[i].x = 0.f; acc[i].y = 0.f; }

#pragma unroll 1
    for (int tap = 0; tap < 27; ++tap) {
        const int dz = tap / 9 - 1;
        const int dy = (tap / 3) % 3 - 1;
        const int dx = tap % 3 - 1;
        const int delta = dz * 4096 + dy * 64 + dx;
        const float2* wp = reinterpret_cast<const float2*>(W + tap * 64 * 64) + lane;

        int offs[VT];
#pragma unroll
        for (int i = 0; i < VT; i++) {
            int v = vids[i];
            int x = v & 63, y = (v >> 6) & 63, z = v >> 12;
            bool inb = (v >= 0) & ((unsigned)(x + dx) < 64u) &
                       ((unsigned)(y + dy) < 64u) & ((unsigned)(z + dz) < 64u);
            int nv = v + delta;
            int o = inb ? owner[nv] : 0;
            offs[i] = (o > 0) ? (nv << 6) : -GUARD;
        }

#pragma unroll 1
        for (int c = 0; c < 64; c += 4) {
            float2 w0 = wp[(c + 0) * 32];
            float2 w1 = wp[(c + 1) * 32];
            float2 w2 = wp[(c + 2) * 32];
            float2 w3 = wp[(c + 3) * 32];
#pragma unroll
            for (int i = 0; i < VT; i++) {
                float4 a = *reinterpret_cast<const float4*>(in + offs[i] + c);
                acc[i].x = fmaf(a.x, w0.x, acc[i].x);
                acc[i].y = fmaf(a.x, w0.y, acc[i].y);
                acc[i].x = fmaf(a.y, w1.x, acc[i].x);
                acc[i].y = fmaf(a.y, w1.y, acc[i].y);
                acc[i].x = fmaf(a.z, w2.x, acc[i].x);
                acc[i].y = fmaf(a.z, w2.y, acc[i].y);
                acc[i].x = fmaf(a.w, w3.x, acc[i].x);
                acc[i].y = fmaf(a.w, w3.y, acc[i].y);
            }
        }
    }

#pragma unroll
    for (int i = 0; i < VT; i++)
        if (vids[i] >= 0)
            *reinterpret_cast<float2*>(out + vids[i] * 64 + 2 * lane) = acc[i];
}

// ======================== dense mma conv, M=32/warp (D=32) ================
// Block = 128 thr = 4 warps; warp owns TWO m16 fragments (rows r and 64+r).
// B fragments loaded once per (tap,chunk,nt) serve 6 MMAs.
template <int CIN, int NT>
__global__ void __launch_bounds__(128) k_convM2(
    const __nv_bfloat16* __restrict__ inH, const __nv_bfloat16* __restrict__ inL,
    float* __restrict__ out,
    const uint2* __restrict__ Bh, const uint2* __restrict__ Bl,
    const float* __restrict__ mask) {
    constexpr int CH = CIN / 16;
    constexpr int COUT = NT * 8;
    __shared__ int s_off[128];

    const int tid = threadIdx.x;
    const int wid = tid >> 5;
    const int lane = tid & 31;
    const int g = lane >> 2;
    const int t2 = (lane & 3) * 2;
    const int vb = blockIdx.x * 128;
    const int r0 = wid * 16 + g;
    const int r1 = r0 + 8;

    float acc0[NT][4], acc1[NT][4];
#pragma unroll
    for (int nt = 0; nt < NT; nt++)
#pragma unroll
        for (int q = 0; q < 4; q++) { acc0[nt][q] = 0.f; acc1[nt][q] = 0.f; }

#pragma unroll 1
    for (int tap = 0; tap < 27; ++tap) {
        const int dz = tap / 9 - 1;
        const int dy = (tap / 3) % 3 - 1;
        const int dxx = tap % 3 - 1;

        __syncthreads();
        {
            int v = vb + tid;
            int vx = v & 31, vy = (v >> 5) & 31, vz = v >> 10;
            bool ok = ((unsigned)(vx + dxx) < 32u) & ((unsigned)(vy + dy) < 32u) &
                      ((unsigned)(vz + dz) < 32u);
            int nv = v + (dz * 32 + dy) * 32 + dxx;
            s_off[tid] = ok ? nv * CIN : -GUARD;
        }
        __syncthreads();

        const int o0 = s_off[r0];
        const int o1 = s_off[r1];
        const int o2 = s_off[64 + r0];
        const int o3 = s_off[64 + r1];

#pragma unroll 1
        for (int c = 0; c < CH; c++) {
            const int kb = c * 16 + t2;
            unsigned ah0[4], al0[4], ah1[4], al1[4];
            ah0[0] = *reinterpret_cast<const unsigned*>(inH + o0 + kb);
            ah0[1] = *reinterpret_cast<const unsigned*>(inH + o1 + kb);
            ah0[2] = *reinterpret_cast<const unsigned*>(inH + o0 + kb + 8);
            ah0[3] = *reinterpret_cast<const unsigned*>(inH + o1 + kb + 8);
            al0[0] = *reinterpret_cast<const unsigned*>(inL + o0 + kb);
            al0[1] = *reinterpret_cast<const unsigned*>(inL + o1 + kb);
            al0[2] = *reinterpret_cast<const unsigned*>(inL + o0 + kb + 8);
            al0[3] = *reinterpret_cast<const unsigned*>(inL + o1 + kb + 8);
            ah1[0] = *reinterpret_cast<const unsigned*>(inH + o2 + kb);
            ah1[1] = *reinterpret_cast<const unsigned*>(inH + o3 + kb);
            ah1[2] = *reinterpret_cast<const unsigned*>(inH + o2 + kb + 8);
            ah1[3] = *reinterpret_cast<const unsigned*>(inH + o3 + kb + 8);
            al1[0] = *reinterpret_cast<const unsigned*>(inL + o2 + kb);
            al1[1] = *reinterpret_cast<const unsigned*>(inL + o3 + kb);
            al1[2] = *reinterpret_cast<const unsigned*>(inL + o2 + kb + 8);
            al1[3] = *reinterpret_cast<const unsigned*>(inL + o3 + kb + 8);

            const uint2* bhp = Bh + ((size_t)(tap * CH + c) * NT) * 32 + lane;
            const uint2* blp = Bl + ((size_t)(tap * CH + c) * NT) * 32 + lane;
#pragma unroll
            for (int nt = 0; nt < NT; nt++) {
                uint2 bh = bhp[nt * 32];
                uint2 bl = blp[nt * 32];
                mma_bf16(acc0[nt], ah0, bh);
                mma_bf16(acc0[nt], al0, bh);
                mma_bf16(acc0[nt], ah0, bl);
                mma_bf16(acc1[nt], ah1, bh);
                mma_bf16(acc1[nt], al1, bh);
                mma_bf16(acc1[nt], ah1, bl);
            }
        }
    }

    const int v0 = vb + r0, v1 = vb + r1;
    const int v2 = vb + 64 + r0, v3 = vb + 64 + r1;
    const float m0 = mask[v0], m1 = mask[v1], m2 = mask[v2], m3 = mask[v3];
#pragma unroll
    for (int nt = 0; nt < NT; nt++) {
        float2 s;
        s.x = acc0[nt][0] * m0; s.y = acc0[nt][1] * m0;
        *reinterpret_cast<float2*>(out + (size_t)v0 * COUT + nt * 8 + t2) = s;
        s.x = acc0[nt][2] * m1; s.y = acc0[nt][3] * m1;
        *reinterpret_cast<float2*>(out + (size_t)v1 * COUT + nt * 8 + t2) = s;
        s.x = acc1[nt][0] * m2; s.y = acc1[nt][1] * m2;
        *reinterpret_cast<float2*>(out + (size_t)v2 * COUT + nt * 8 + t2) = s;
        s.x = acc1[nt][2] * m3; s.y = acc1[nt][3] * m3;
        *reinterpret_cast<float2*>(out + (size_t)v3 * COUT + nt * 8 + t2) = s;
    }
}

// ======================== dense mma conv, N-split (D=16) ==================
// Block = 64 voxels (M=16/warp); blockIdx.y selects a group of NTG n-tiles
// out of NTOT (COUT = NTOT*8).
template <int CIN, int LOGD, int NTG, int NTOT>
__global__ void __launch_bounds__(128) k_convM(
    const __nv_bfloat16* __restrict__ inH, const __nv_bfloat16* __restrict__ inL,
    float* __restrict__ out,
    const uint2* __restrict__ Bh, const uint2* __restrict__ Bl,
    const float* __restrict__ mask) {
    constexpr int CH = CIN / 16;
    constexpr int COUT = NTOT * 8;
    constexpr int DD = 1 << LOGD;
    __shared__ int s_off[64];

    const int tid = threadIdx.x;
    const int wid = tid >> 5;
    const int lane = tid & 31;
    const int g = lane >> 2;
    const int t2 = (lane & 3) * 2;
    const int vb = blockIdx.x * 64;
    const int nb = blockIdx.y * NTG;
    const int r0 = wid * 16 + g;
    const int r1 = r0 + 8;

    float acc[NTG][4];
#pragma unroll
    for (int nt = 0; nt < NTG; nt++)
#pragma unroll
        for (int q = 0; q < 4; q++) acc[nt][q] = 0.f;

#pragma unroll 1
    for (int tap = 0; tap < 27; ++tap) {
        const int dz = tap / 9 - 1;
        const int dy = (tap / 3) % 3 - 1;
        const int dxx = tap % 3 - 1;

        __syncthreads();
        if (tid < 64) {
            int v = vb + tid;
            int vx = v & (DD - 1), vy = (v >> LOGD) & (DD - 1), vz = v >> (2 * LOGD);
            bool ok = ((unsigned)(vx + dxx) < (unsigned)DD) &
                      ((unsigned)(vy + dy) < (unsigned)DD) &
                      ((unsigned)(vz + dz) < (unsigned)DD);
            int nv = v + (dz * DD + dy) * DD + dxx;
            s_off[tid] = ok ? nv * CIN : -GUARD;
        }
        __syncthreads();

        const int o0 = s_off[r0];
        const int o1 = s_off[r1];

#pragma unroll 1
        for (int c = 0; c < CH; c++) {
            const int kb = c * 16 + t2;
            unsigned ah[4], al[4];
            ah[0] = *reinterpret_cast<const unsigned*>(inH + o0 + kb);
            ah[1] = *reinterpret_cast<const unsigned*>(inH + o1 + kb);
            ah[2] = *reinterpret_cast<const unsigned*>(inH + o0 + kb + 8);
            ah[3] = *reinterpret_cast<const unsigned*>(inH + o1 + kb + 8);
            al[0] = *reinterpret_cast<const unsigned*>(inL + o0 + kb);
            al[1] = *reinterpret_cast<const unsigned*>(inL + o1 + kb);
            al[2] = *reinterpret_cast<const unsigned*>(inL + o0 + kb + 8);
            al[3] = *reinterpret_cast<const unsigned*>(inL + o1 + kb + 8);

            const uint2* bhp = Bh + ((size_t)(tap * CH + c) * NTOT + nb) * 32 + lane;
            const uint2* blp = Bl + ((size_t)(tap * CH + c) * NTOT + nb) * 32 + lane;
#pragma unroll
            for (int nt = 0; nt < NTG; nt++) {
                uint2 bh = bhp[nt * 32];
                uint2 bl = blp[nt * 32];
                mma_bf16(acc[nt], ah, bh);
                mma_bf16(acc[nt], al, bh);
                mma_bf16(acc[nt], ah, bl);
            }
        }
    }

    const int v0 = vb + r0;
    const int v1 = vb + r1;
    const float m0 = mask[v0];
    const float m1 = mask[v1];
#pragma unroll
    for (int nt = 0; nt < NTG; nt++) {
        float2 lo_st, hi_st;
        lo_st.x = acc[nt][0] * m0;
        lo_st.y = acc[nt][1] * m0;
        hi_st.x = acc[nt][2] * m1;
        hi_st.y = acc[nt][3] * m1;
        *reinterpret_cast<float2*>(out + (size_t)v0 * COUT + (nb + nt) * 8 + t2) = lo_st;
        *reinterpret_cast<float2*>(out + (size_t)v1 * COUT + (nb + nt) * 8 + t2) = hi_st;
    }
}

// ======================== scalar dense conv (tail) ========================
template <int CIN, int COUT, int WX, int WC, int COT, int XTT, bool CONTIG>
__global__ void __launch_bounds__(32 * WX * WC) k_convd(
    const float* __restrict__ in, float* __restrict__ out,
    const float* __restrict__ W, const float* __restrict__ mask, int D) {
    const int lane = threadIdx.x & 31;
    const int wrp = threadIdx.x >> 5;
    const int wc = wrp % WC;
    const int wx = wrp / WC;
    const int z = blockIdx.z, y = blockIdx.y;
    const int x0 = blockIdx.x * (WX * XTT) + wx * XTT;
    const int co0 = CONTIG ? (lane + 32 * wc) * COT : (lane + 32 * wc);

    float acc[XTT][COT];
#pragma unroll
    for (int i = 0; i < XTT; i++)
#pragma unroll
        for (int j = 0; j < COT; j++) acc[i][j] = 0.f;

#pragma unroll 1
    for (int r = 0; r < 9; r++) {
        const int dz = r / 3 - 1, dy = r % 3 - 1;
        const int zz = z + dz, yy = y + dy;
        if ((unsigned)zz >= (unsigned)D || (unsigned)yy >= (unsigned)D) continue;
        const int rowbase = ((zz * D + yy) * D) * CIN;

        int ox[XTT + 2];
#pragma unroll
        for (int i = 0; i < XTT + 2; i++) {
            int gx = x0 - 1 + i;
            ox[i] = ((unsigned)gx < (unsigned)D) ? rowbase + gx * CIN : -GUARD;
        }

#pragma unroll 1
        for (int c = 0; c < CIN; c += 4) {
            float4 a[XTT + 2];
#pragma unroll
            for (int i = 0; i < XTT + 2; i++)
                a[i] = *reinterpret_cast<const float4*>(in + ox[i] + c);
#pragma unroll
            for (int dx = 0; dx < 3; dx++) {
                const float* wp = W + (size_t)((r * 3 + dx) * CIN) * COUT + co0;
                float wv[4][COT];
#pragma unroll
                for (int q = 0; q < 4; q++) {
                    if (CONTIG && COT == 2) {
                        float2 tt = *reinterpret_cast<const float2*>(wp + (c + q) * COUT);
                        wv[q][0] = tt.x;
                        wv[q][1] = tt.y;
                    } else {
#pragma unroll
                        for (int j = 0; j < COT; j++)
                            wv[q][j] = wp[(c + q) * COUT + j * 32 * WC];
                    }
                }
#pragma unroll
                for (int i = 0; i < XTT; i++) {
#pragma unroll
                    for (int j = 0; j < COT; j++) {
                        acc[i][j] = fmaf(a[i + dx].x, wv[0][j], acc[i][j]);
                        acc[i][j] = fmaf(a[i + dx].y, wv[1][j], acc[i][j]);
                        acc[i][j] = fmaf(a[i + dx].z, wv[2][j], acc[i][j]);
                        acc[i][j] = fmaf(a[i + dx].w, wv[3][j], acc[i][j]);
                    }
                }
            }
        }
    }

    const int vb = (z * D + y) * D;
#pragma unroll
    for (int i = 0; i < XTT; i++) {
        int gx = x0 + i;
        float m = mask[vb + gx];
        float* op = out + (size_t)(vb + gx) * COUT + co0;
        if (CONTIG && COT == 2) {
            float2 tt;
            tt.x = acc[i][0] * m;
            tt.y = acc[i][1] * m;
            *reinterpret_cast<float2*>(op) = tt;
        } else {
#pragma unroll
            for (int j = 0; j < COT; j++) op[j * 32 * WC] = acc[i][j] * m;
        }
    }
}

// ======================== masked 2x2x2 max pool ===========================
__global__ void k_pool(const float* __restrict__ in, const float* __restrict__ im,
                       float* __restrict__ out, float* __restrict__ om,
                       int Do, int C) {
    int idx = blockIdx.x * blockDim.x + threadIdx.x;
    int total = Do * Do * Do * C;
    if (idx >= total) return;
    int c = idx % C;
    int v = idx / C;
    int xo = v % Do;
    int yo = (v / Do) % Do;
    int zo = v / (Do * Do);
    int Di = Do * 2;
    float best = -3.4e38f;
    bool any = false;
#pragma unroll
    for (int a = 0; a < 2; a++)
#pragma unroll
        for (int b = 0; b < 2; b++)
#pragma unroll
            for (int d = 0; d < 2; d++) {
                int vi = ((2 * zo + a) * Di + (2 * yo + b)) * Di + (2 * xo + d);
                if (im[vi] > 0.f) {
                    any = true;
                    float t = in[vi * C + c];
                    best = t > best ? t : best;
                }
            }
    out[v * C + c] = any ? best : 0.f;
    if (c == 0) om[v] = any ? 1.f : 0.f;
}

// ---------------------------------------------------------------------------
extern "C" void kernel_launch(void* const* d_in, const int* in_sizes, int n_in,
                              void* d_out, int out_size) {
    const float* feat = (const float*)d_in[0];
    const int* coors = (const int*)d_in[1];
    const float* W[14];
    for (int i = 0; i < 14; i++) W[i] = (const float*)d_in[2 + i];

    float *A, *B, *MA, *MB, *ZP;
    int* OWN;
    __nv_bfloat16 *HI, *LO;
    uint2 *PBH2, *PBL2, *PBH3, *PBL3, *PBH4, *PBL4, *PBH5, *PBL5;
    cudaGetSymbolAddress((void**)&A, g_bufA);
    cudaGetSymbolAddress((void**)&B, g_bufB);
    cudaGetSymbolAddress((void**)&MA, g_maskA);
    cudaGetSymbolAddress((void**)&MB, g_maskB);
    cudaGetSymbolAddress((void**)&OWN, g_owner);
    cudaGetSymbolAddress((void**)&HI, g_hi);
    cudaGetSymbolAddress((void**)&LO, g_lo);
    cudaGetSymbolAddress((void**)&PBH2, g_pbh2);
    cudaGetSymbolAddress((void**)&PBL2, g_pbl2);
    cudaGetSymbolAddress((void**)&PBH3, g_pbh3);
    cudaGetSymbolAddress((void**)&PBL3, g_pbl3);
    cudaGetSymbolAddress((void**)&PBH4, g_pbh4);
    cudaGetSymbolAddress((void**)&PBL4, g_pbl4);
    cudaGetSymbolAddress((void**)&PBH5, g_pbh5);
    cudaGetSymbolAddress((void**)&PBL5, g_pbl5);
    ZP = A;      // zero prefix of g_bufA doubles as conv_s0's zero page
    A += GUARD;
    B += GUARD;

    const int N = in_sizes[0] / 3;
    const int sb = (N + 39) / 40;

    // Launch index:            0        1        2          3 (ncu capture)
    k_scatter<<<(N + 255) / 256, 256>>>(coors, N, OWN);
    k_build<<<(VOL0 + 255) / 256, 256>>>(OWN, MA);
    k_conv_s0<<<sb, 128>>>(OWN, feat, B, W[0], ZP);
    k_conv_s64<<<sb, 128>>>(OWN, B, A, W[1]);

    // Weight prepacks for mma convs (after s64 to keep profile slot)
    k_pb<<<(27 * 4 * 12 * 32 + 255) / 256, 256>>>(W[2], PBH2, PBL2, 64, 4, 12, 96);
    k_pb<<<(27 * 6 * 12 * 32 + 255) / 256, 256>>>(W[3], PBH3, PBL3, 96, 6, 12, 96);
    k_pb<<<(27 * 6 * 16 * 32 + 255) / 256, 256>>>(W[4], PBH4, PBL4, 96, 6, 16, 128);
    k_pb<<<(27 * 8 * 16 * 32 + 255) / 256, 256>>>(W[5], PBH5, PBL5, 128, 8, 16, 128);

    k_pool<<<(32 * 32 * 32 * 64 + 255) / 256, 256>>>(A, MA, B, MB, 32, 64);

    // D=32: dense mma convs (M=32/warp)
    k_split<<<(32768 * 64 + 255) / 256, 256>>>(B, HI + GUARD, LO + GUARD, 32768 * 64);
    k_convM2<64, 12><<<256, 128>>>(HI + GUARD, LO + GUARD, A, PBH2, PBL2, MB);
    k_split<<<(32768 * 96 + 255) / 256, 256>>>(A, HI + GUARD, LO + GUARD, 32768 * 96);
    k_convM2<96, 12><<<256, 128>>>(HI + GUARD, LO + GUARD, B, PBH3, PBL3, MB);
    k_pool<<<(16 * 16 * 16 * 96 + 255) / 256, 256>>>(B, MB, A, MA, 16, 96);

    // D=16: dense mma convs, N-split grid (128 blocks each)
    k_split<<<(4096 * 96 + 255) / 256, 256>>>(A, HI + GUARD, LO + GUARD, 4096 * 96);
    k_convM<96, 4, 8, 16><<<dim3(64, 2), 128>>>(HI + GUARD, LO + GUARD, B, PBH4, PBL4, MA);
    k_split<<<(4096 * 128 + 255) / 256, 256>>>(B, HI + GUARD, LO + GUARD, 4096 * 128);
    k_convM<128, 4, 8, 16><<<dim3(64, 2), 128>>>(HI + GUARD, LO + GUARD, A, PBH5, PBL5, MA);
    k_pool<<<(8 * 8 * 8 * 128 + 255) / 256, 256>>>(A, MA, B, MB, 8, 128);

    // D=8 (scalar tail)
    k_convd<128, 160, 1, 5, 1, 1, false><<<dim3(8, 8, 8), 160>>>(B, A, W[6], MB, 8);
    k_convd<160, 160, 1, 5, 1, 1, false><<<dim3(8, 8, 8), 160>>>(A, B, W[7], MB, 8);
    k_pool<<<(4 * 4 * 4 * 160 + 255) / 256, 256>>>(B, MB, A, MA, 4, 160);

    // D=4
    k_convd<160, 192, 1, 3, 2, 1, true><<<dim3(4, 4, 4), 96>>>(A, B, W[8], MA, 4);
    k_convd<192, 192, 1, 3, 2, 1, true><<<dim3(4, 4, 4), 96>>>(B, A, W[9], MA, 4);
    k_pool<<<(2 * 2 * 2 * 192 + 255) / 256, 256>>>(A, MA, B, MB, 2, 192);

    // D=2
    k_convd<192, 224, 1, 7, 1, 1, false><<<dim3(2, 2, 2), 224>>>(B, A, W[10], MB, 2);
    k_convd<224, 224, 1, 7, 1, 1, false><<<dim3(2, 2, 2), 224>>>(A, B, W[11], MB, 2);
    k_pool<<<(1 * 224 + 255) / 256, 256>>>(B, MB, A, MA, 1, 224);

    // D=1 -> final output straight into d_out
    k_convd<224, 256, 1, 4, 2, 1, true><<<dim3(1, 1, 1), 128>>>(A, B, W[12], MA, 1);
    k_convd<256, 256, 1, 4, 2, 1, true><<<dim3(1, 1, 1), 128>>>(B, (float*)d_out, W[13], MA, 1);
}